// round 2
// baseline (speedup 1.0000x reference)
#include <cuda_runtime.h>
#include <math.h>

// Problem constants
#define BATCH 16384
#define D0    1024
#define D1    1024
#define D2    512
#define KDIM  6144     // 1024 * 6 feature planes (T1..T5 + base x); T0 folded into bias
#define LN_EPS 1e-5f

// ---------------- scratch (device globals; no runtime allocation) -------------
__device__ float g_F  [(size_t)BATCH * KDIM];    // feature matrix, reused for both layers
__device__ float g_H  [(size_t)BATCH * D1];      // layer-1 output (pre-LN)
__device__ float g_Wt1[(size_t)KDIM * D1];       // transposed weights layer 1: [k][o]
__device__ float g_Wt2[(size_t)KDIM * D2];       // transposed weights layer 2: [k][o]
__device__ float g_b1 [D1];                      // bias + T0 fold, layer 1
__device__ float g_b2 [D2];                      // bias + T0 fold, layer 2

// ---------------- weight prep: Wt[k][o] from coeff[o][i][6] + base_w[o][i] ----
// k = d*1024 + i ; plane d<5 -> coeff[o,i,d+1] ; plane 5 -> base_w[o,i]
__global__ void k_build_wt(const float* __restrict__ coeff,
                           const float* __restrict__ base_w,
                           float* __restrict__ Wt, int O)
{
    __shared__ float tile[32][33];
    int k0 = blockIdx.x * 32;
    int o0 = blockIdx.y * 32;
    int tx = threadIdx.x;           // 0..31
    for (int r = threadIdx.y; r < 32; r += 8) {
        int o = o0 + r;
        int k = k0 + tx;
        int d = k >> 10;
        int i = k & 1023;
        float v = (d < 5) ? coeff[((size_t)o * 1024 + i) * 6 + d + 1]
                          : base_w[(size_t)o * 1024 + i];
        tile[r][tx] = v;
    }
    __syncthreads();
    for (int r = threadIdx.y; r < 32; r += 8) {
        int k = k0 + r;
        int o = o0 + tx;
        Wt[(size_t)k * O + o] = tile[tx][r];
    }
}

// bias_eff[o] = bias[o] + sum_i coeff[o,i,0]
__global__ __launch_bounds__(256) void k_bias_eff(const float* __restrict__ coeff,
                                                  const float* __restrict__ bias,
                                                  float* __restrict__ out, int I)
{
    int o = blockIdx.x;
    int tid = threadIdx.x;
    float s = 0.f;
    for (int i = tid; i < I; i += 256)
        s += coeff[((size_t)o * I + i) * 6];
    // block reduce
    __shared__ float sm[8];
    for (int off = 16; off > 0; off >>= 1) s += __shfl_down_sync(0xffffffffu, s, off);
    if ((tid & 31) == 0) sm[tid >> 5] = s;
    __syncthreads();
    if (tid < 8) {
        s = sm[tid];
        for (int off = 4; off > 0; off >>= 1) s += __shfl_down_sync(0xffu, s, off);
        if (tid == 0) out[o] = bias[o] + s;
    }
}

// ---------------- input features: planes {T1..T5(tanh(t)), t} with t=tanh(x) --
__global__ __launch_bounds__(256) void k_feat_in(const float* __restrict__ x,
                                                 float* __restrict__ F)
{
    int idx = blockIdx.x * 256 + threadIdx.x;
    if (idx >= BATCH * D0) return;
    int b = idx >> 10;
    int i = idx & 1023;
    float t  = tanhf(x[idx]);
    float xn = tanhf(t);
    float T1 = xn;
    float T2 = 2.f * xn * xn - 1.f;
    float T3 = 2.f * xn * T2 - T1;
    float T4 = 2.f * xn * T3 - T2;
    float T5 = 2.f * xn * T4 - T3;
    size_t base = (size_t)b * KDIM + i;
    F[base + 0 * 1024] = T1;
    F[base + 1 * 1024] = T2;
    F[base + 2 * 1024] = T3;
    F[base + 3 * 1024] = T4;
    F[base + 4 * 1024] = T5;
    F[base + 5 * 1024] = t;
}

// ---------------- LayerNorm + SiLU + features for layer 2 ---------------------
__global__ __launch_bounds__(256) void k_ln_silu_feat(const float* __restrict__ H,
                                                      const float* __restrict__ gamma,
                                                      const float* __restrict__ beta,
                                                      float* __restrict__ F)
{
    int b = blockIdx.x;
    int tid = threadIdx.x;
    const float* h = H + (size_t)b * D1;

    float v[4];
    float s = 0.f, sq = 0.f;
#pragma unroll
    for (int j = 0; j < 4; j++) {
        v[j] = h[tid + j * 256];
        s  += v[j];
        sq += v[j] * v[j];
    }
    // block reduce (sum, sumsq)
    __shared__ float sm_s[8], sm_q[8];
    for (int off = 16; off > 0; off >>= 1) {
        s  += __shfl_down_sync(0xffffffffu, s,  off);
        sq += __shfl_down_sync(0xffffffffu, sq, off);
    }
    if ((tid & 31) == 0) { sm_s[tid >> 5] = s; sm_q[tid >> 5] = sq; }
    __syncthreads();
    __shared__ float s_mu, s_rs;
    if (tid < 8) {
        s  = sm_s[tid];
        sq = sm_q[tid];
        for (int off = 4; off > 0; off >>= 1) {
            s  += __shfl_down_sync(0xffu, s,  off);
            sq += __shfl_down_sync(0xffu, sq, off);
        }
        if (tid == 0) {
            float mu  = s * (1.f / D1);
            float var = sq * (1.f / D1) - mu * mu;
            s_mu = mu;
            s_rs = rsqrtf(var + LN_EPS);
        }
    }
    __syncthreads();
    float mu = s_mu, rs = s_rs;

#pragma unroll
    for (int j = 0; j < 4; j++) {
        int i = tid + j * 256;
        float y  = (v[j] - mu) * rs * gamma[i] + beta[i];
        float sg = 1.f / (1.f + expf(-y));
        float sv = y * sg;                 // SiLU
        float xn = tanhf(sv);
        float T1 = xn;
        float T2 = 2.f * xn * xn - 1.f;
        float T3 = 2.f * xn * T2 - T1;
        float T4 = 2.f * xn * T3 - T2;
        float T5 = 2.f * xn * T4 - T3;
        size_t base = (size_t)b * KDIM + i;
        F[base + 0 * 1024] = T1;
        F[base + 1 * 1024] = T2;
        F[base + 2 * 1024] = T3;
        F[base + 3 * 1024] = T4;
        F[base + 4 * 1024] = T5;
        F[base + 5 * 1024] = sv;
    }
}

// ---------------- register-blocked SGEMM: C[M,N] = A[M,K] * B[K,N] + bias -----
#define BM 128
#define BN 128
#define BK 8
#define TM 8
#define TN 8

__global__ __launch_bounds__(256, 2) void sgemm_bias(const float* __restrict__ A,
                                                     const float* __restrict__ B,
                                                     const float* __restrict__ bias,
                                                     float* __restrict__ C,
                                                     int M, int N, int K)
{
    __shared__ __align__(16) float As[BK][BM];
    __shared__ __align__(16) float Bs[BK][BN];

    int tid = threadIdx.x;
    int block_row = blockIdx.y * BM;
    int block_col = blockIdx.x * BN;

    int a_row = tid >> 1;            // 0..127
    int a_col = (tid & 1) * 4;       // 0 or 4
    int b_row = tid >> 5;            // 0..7
    int b_col = (tid & 31) * 4;      // 0..124

    int tx = tid & 15;
    int ty = tid >> 4;

    float acc[TM][TN];
#pragma unroll
    for (int i = 0; i < TM; i++)
#pragma unroll
        for (int j = 0; j < TN; j++) acc[i][j] = 0.f;

    const float* Aptr = A + (size_t)(block_row + a_row) * K + a_col;
    const float* Bptr = B + b_col + block_col;

    for (int k0 = 0; k0 < K; k0 += BK) {
        float4 av = *reinterpret_cast<const float4*>(Aptr + k0);
        As[a_col + 0][a_row] = av.x;
        As[a_col + 1][a_row] = av.y;
        As[a_col + 2][a_row] = av.z;
        As[a_col + 3][a_row] = av.w;
        float4 bv = *reinterpret_cast<const float4*>(Bptr + (size_t)(k0 + b_row) * N);
        *reinterpret_cast<float4*>(&Bs[b_row][b_col]) = bv;
        __syncthreads();

#pragma unroll
        for (int kk = 0; kk < BK; kk++) {
            float4 a0 = *reinterpret_cast<const float4*>(&As[kk][ty * TM]);
            float4 a1 = *reinterpret_cast<const float4*>(&As[kk][ty * TM + 4]);
            float4 b0 = *reinterpret_cast<const float4*>(&Bs[kk][tx * TN]);
            float4 b1 = *reinterpret_cast<const float4*>(&Bs[kk][tx * TN + 4]);
            float ar[TM] = {a0.x, a0.y, a0.z, a0.w, a1.x, a1.y, a1.z, a1.w};
            float br[TN] = {b0.x, b0.y, b0.z, b0.w, b1.x, b1.y, b1.z, b1.w};
#pragma unroll
            for (int i = 0; i < TM; i++)
#pragma unroll
                for (int j = 0; j < TN; j++)
                    acc[i][j] = fmaf(ar[i], br[j], acc[i][j]);
        }
        __syncthreads();
    }

    // epilogue: add bias, store
    float bb[TN];
#pragma unroll
    for (int j = 0; j < TN; j++) bb[j] = bias[block_col + tx * TN + j];

#pragma unroll
    for (int i = 0; i < TM; i++) {
        int row = block_row + ty * TM + i;
        float* Crow = C + (size_t)row * N + block_col + tx * TN;
        float4 o0, o1;
        o0.x = acc[i][0] + bb[0];
        o0.y = acc[i][1] + bb[1];
        o0.z = acc[i][2] + bb[2];
        o0.w = acc[i][3] + bb[3];
        o1.x = acc[i][4] + bb[4];
        o1.y = acc[i][5] + bb[5];
        o1.z = acc[i][6] + bb[6];
        o1.w = acc[i][7] + bb[7];
        *reinterpret_cast<float4*>(Crow)     = o0;
        *reinterpret_cast<float4*>(Crow + 4) = o1;
    }
}

// ---------------- host launcher ----------------------------------------------
extern "C" void kernel_launch(void* const* d_in, const int* in_sizes, int n_in,
                              void* d_out, int out_size)
{
    const float* x       = (const float*)d_in[0];
    const float* coeff1  = (const float*)d_in[1];
    const float* base_w1 = (const float*)d_in[2];
    const float* bias1   = (const float*)d_in[3];
    const float* gamma   = (const float*)d_in[4];
    const float* beta    = (const float*)d_in[5];
    const float* coeff2  = (const float*)d_in[6];
    const float* base_w2 = (const float*)d_in[7];
    const float* bias2   = (const float*)d_in[8];
    float* out = (float*)d_out;

    float *F, *H, *Wt1, *Wt2, *b1, *b2;
    cudaGetSymbolAddress((void**)&F,   g_F);
    cudaGetSymbolAddress((void**)&H,   g_H);
    cudaGetSymbolAddress((void**)&Wt1, g_Wt1);
    cudaGetSymbolAddress((void**)&Wt2, g_Wt2);
    cudaGetSymbolAddress((void**)&b1,  g_b1);
    cudaGetSymbolAddress((void**)&b2,  g_b2);

    // 1. weight prep
    {
        dim3 blk(32, 8);
        dim3 g1(KDIM / 32, D1 / 32);
        k_build_wt<<<g1, blk>>>(coeff1, base_w1, Wt1, D1);
        dim3 g2(KDIM / 32, D2 / 32);
        k_build_wt<<<g2, blk>>>(coeff2, base_w2, Wt2, D2);
        k_bias_eff<<<D1, 256>>>(coeff1, bias1, b1, D0);
        k_bias_eff<<<D2, 256>>>(coeff2, bias2, b2, D1);
    }

    // 2. input features
    k_feat_in<<<(BATCH * D0 + 255) / 256, 256>>>(x, F);

    // 3. GEMM1: H = F * Wt1 + b1   (M=16384, N=1024, K=6144)
    {
        dim3 grid(D1 / BN, BATCH / BM);
        sgemm_bias<<<grid, 256>>>(F, Wt1, b1, H, BATCH, D1, KDIM);
    }

    // 4. LayerNorm + SiLU + features (reuse F)
    k_ln_silu_feat<<<BATCH, 256>>>(H, gamma, beta, F);

    // 5. GEMM2: out = F * Wt2 + b2  (M=16384, N=512, K=6144)
    {
        dim3 grid(D2 / BN, BATCH / BM);
        sgemm_bias<<<grid, 256>>>(F, Wt2, b2, out, BATCH, D2, KDIM);
    }
}

// round 7
// speedup vs baseline: 3.6384x; 3.6384x over previous
#include <cuda_runtime.h>
#include <cuda_fp16.h>
#include <cstdint>
#include <math.h>

// Problem constants
#define BATCH 16384
#define D0    1024
#define D1    1024
#define D2    512
#define KDIM  6144     // 6 feature planes (T1..T5 + base); T0 folded into bias
#define LN_EPS 1e-5f

// GEMM tiling
#define BK    32
#define ROWB  80                         // bytes per smem row: 32 fp16 (64B) + 16B pad
#define MAT_B (128 * ROWB)               // one 128x32 fp16 tile = 10240 B
#define STAGE_BYTES (3 * MAT_B)          // F, Wh, Wl
#define STAGES 3
#define GEMM_SMEM (STAGES * STAGE_BYTES) // 92160 B

// ---------------- scratch (device globals; no runtime allocation) -------------
__device__ __half g_F  [(size_t)BATCH * KDIM];   // features fp16 (single plane)
__device__ float  g_H  [(size_t)BATCH * D1];     // layer-1 output (pre-LN)
__device__ __half g_W1h[(size_t)D1 * KDIM];
__device__ __half g_W1l[(size_t)D1 * KDIM];
__device__ __half g_W2h[(size_t)D2 * KDIM];
__device__ __half g_W2l[(size_t)D2 * KDIM];
__device__ float  g_b1[D1];
__device__ float  g_b2[D2];

// ---------------- helpers -----------------------------------------------------
__device__ __forceinline__ uint32_t smem_u32(const void* p) {
    uint32_t a;
    asm("{ .reg .u64 t; cvta.to.shared.u64 t, %1; cvt.u32.u64 %0, t; }" : "=r"(a) : "l"(p));
    return a;
}

#define CP_ASYNC16(dst, src) \
    asm volatile("cp.async.cg.shared.global [%0], [%1], 16;" \
                 :: "r"(dst), "l"(src) : "memory")
#define CP_COMMIT() asm volatile("cp.async.commit_group;" ::: "memory")
#define CP_WAIT(n)  asm volatile("cp.async.wait_group %0;" :: "n"(n) : "memory")

__device__ __forceinline__ void ldsm4(uint32_t addr, uint32_t& r0, uint32_t& r1,
                                      uint32_t& r2, uint32_t& r3) {
    asm volatile("ldmatrix.sync.aligned.m8n8.x4.shared.b16 {%0,%1,%2,%3}, [%4];"
                 : "=r"(r0), "=r"(r1), "=r"(r2), "=r"(r3) : "r"(addr));
}

__device__ __forceinline__ void mma16816(float* c, const uint32_t* a,
                                         uint32_t b0, uint32_t b1) {
    asm volatile("mma.sync.aligned.m16n8k16.row.col.f32.f16.f16.f32 "
                 "{%0,%1,%2,%3}, {%4,%5,%6,%7}, {%8,%9}, {%0,%1,%2,%3};"
                 : "+f"(c[0]), "+f"(c[1]), "+f"(c[2]), "+f"(c[3])
                 : "r"(a[0]), "r"(a[1]), "r"(a[2]), "r"(a[3]), "r"(b0), "r"(b1));
}

__device__ __forceinline__ void split2h(float v, __half& h, __half& l) {
    h = __float2half_rn(v);
    l = __float2half_rn(v - __half2float(h));
}

// ---------------- weight prep: W[o][k] hi/lo fp16 -----------------------------
// k = d*1024 + i ; plane d<5 -> coeff[o,i,d+1] ; plane 5 -> base_w[o,i]
__global__ __launch_bounds__(256) void k_wprep(const float* __restrict__ coeff,
                                               const float* __restrict__ basew,
                                               __half* __restrict__ Wh,
                                               __half* __restrict__ Wl, int I)
{
    int o = blockIdx.x;
    int K = 6 * I;
    for (int i = threadIdx.x; i < I; i += 256) {
        const float* cp = coeff + ((size_t)o * I + i) * 6;
        float bw = basew[(size_t)o * I + i];
#pragma unroll
        for (int d = 0; d < 5; d++) {
            __half h, l;
            split2h(cp[d + 1], h, l);
            size_t idx = (size_t)o * K + d * I + i;
            Wh[idx] = h; Wl[idx] = l;
        }
        __half h, l;
        split2h(bw, h, l);
        size_t idx = (size_t)o * K + 5 * I + i;
        Wh[idx] = h; Wl[idx] = l;
    }
}

// bias_eff[o] = bias[o] + sum_i coeff[o,i,0]
__global__ __launch_bounds__(256) void k_bias_eff(const float* __restrict__ coeff,
                                                  const float* __restrict__ bias,
                                                  float* __restrict__ out, int I)
{
    int o = blockIdx.x;
    int tid = threadIdx.x;
    float s = 0.f;
    for (int i = tid; i < I; i += 256)
        s += coeff[((size_t)o * I + i) * 6];
    __shared__ float sm[8];
    for (int off = 16; off > 0; off >>= 1) s += __shfl_down_sync(0xffffffffu, s, off);
    if ((tid & 31) == 0) sm[tid >> 5] = s;
    __syncthreads();
    if (tid < 8) {
        s = sm[tid];
        for (int off = 4; off > 0; off >>= 1) s += __shfl_down_sync(0xffu, s, off);
        if (tid == 0) out[o] = bias[o] + s;
    }
}

// ---------------- feature writers ---------------------------------------------
__device__ __forceinline__ void write_feats(float inp, size_t base,
                                            __half* __restrict__ F)
{
    float xn = tanhf(inp);
    float T1 = xn;
    float T2 = 2.f * xn * xn - 1.f;
    float T3 = 2.f * xn * T2 - T1;
    float T4 = 2.f * xn * T3 - T2;
    float T5 = 2.f * xn * T4 - T3;
    F[base + 0 * 1024] = __float2half_rn(T1);
    F[base + 1 * 1024] = __float2half_rn(T2);
    F[base + 2 * 1024] = __float2half_rn(T3);
    F[base + 3 * 1024] = __float2half_rn(T4);
    F[base + 4 * 1024] = __float2half_rn(T5);
    F[base + 5 * 1024] = __float2half_rn(inp);
}

__global__ __launch_bounds__(256) void k_feat_in(const float* __restrict__ x,
                                                 __half* __restrict__ F)
{
    int idx = blockIdx.x * 256 + threadIdx.x;
    if (idx >= BATCH * D0) return;
    int b = idx >> 10;
    int i = idx & 1023;
    float t = tanhf(x[idx]);
    write_feats(t, (size_t)b * KDIM + i, F);
}

__global__ __launch_bounds__(256) void k_ln_silu_feat(const float* __restrict__ H,
                                                      const float* __restrict__ gamma,
                                                      const float* __restrict__ beta,
                                                      __half* __restrict__ F)
{
    int b = blockIdx.x;
    int tid = threadIdx.x;
    const float* h = H + (size_t)b * D1;

    float v[4];
    float s = 0.f, sq = 0.f;
#pragma unroll
    for (int j = 0; j < 4; j++) {
        v[j] = h[tid + j * 256];
        s  += v[j];
        sq += v[j] * v[j];
    }
    __shared__ float sm_s[8], sm_q[8];
    for (int off = 16; off > 0; off >>= 1) {
        s  += __shfl_down_sync(0xffffffffu, s,  off);
        sq += __shfl_down_sync(0xffffffffu, sq, off);
    }
    if ((tid & 31) == 0) { sm_s[tid >> 5] = s; sm_q[tid >> 5] = sq; }
    __syncthreads();
    __shared__ float s_mu, s_rs;
    if (tid < 8) {
        s = sm_s[tid]; sq = sm_q[tid];
        for (int off = 4; off > 0; off >>= 1) {
            s  += __shfl_down_sync(0xffu, s,  off);
            sq += __shfl_down_sync(0xffu, sq, off);
        }
        if (tid == 0) {
            float mu = s * (1.f / D1);
            float var = sq * (1.f / D1) - mu * mu;
            s_mu = mu;
            s_rs = rsqrtf(var + LN_EPS);
        }
    }
    __syncthreads();
    float mu = s_mu, rs = s_rs;

#pragma unroll
    for (int j = 0; j < 4; j++) {
        int i = tid + j * 256;
        float y  = (v[j] - mu) * rs * gamma[i] + beta[i];
        float sg = 1.f / (1.f + expf(-y));
        float sv = y * sg;
        write_feats(sv, (size_t)b * KDIM + i, F);
    }
}

// ---------------- HMMA GEMM: C[M,N] = F * W^T + bias (fp16 split-W, 2 pass) ---
// F[M,K] fp16; Wh/Wl[N,K] fp16; C fp32. 128x128x32 tiles, 3-stage cp.async.
__global__ __launch_bounds__(256, 2) void gemm_hsplit(
    const __half* __restrict__ F,
    const __half* __restrict__ Wh, const __half* __restrict__ Wl,
    const float* __restrict__ bias, float* __restrict__ C, int N, int K)
{
    extern __shared__ char smem_raw[];
    uint32_t sbase = smem_u32(smem_raw);
    const int tid  = threadIdx.x;
    const int wid  = tid >> 5, lane = tid & 31;
    const int wm   = wid >> 1;       // 0..3 -> m offset 32*wm
    const int wn   = wid & 1;        // 0..1 -> n offset 64*wn
    const int brow = blockIdx.y * 128;
    const int bcol = blockIdx.x * 128;

    const __half* Ap  = F  + (size_t)brow * K;
    const __half* Bhp = Wh + (size_t)bcol * K;
    const __half* Blp = Wl + (size_t)bcol * K;

    float acc[2][8][4];
#pragma unroll
    for (int a = 0; a < 2; a++)
#pragma unroll
        for (int b = 0; b < 8; b++)
#pragma unroll
            for (int q = 0; q < 4; q++) acc[a][b][q] = 0.f;

    // fill one stage: 3 matrices x 128 rows x 64B (4x16B chunks/row)
    auto fill = [&](int stage, int k0) {
        uint32_t st = sbase + stage * STAGE_BYTES;
        const __half* srcs[3] = {Ap, Bhp, Blp};
#pragma unroll
        for (int m = 0; m < 3; m++) {
#pragma unroll
            for (int j = 0; j < 2; j++) {
                int c   = tid + 256 * j;         // 0..511
                int row = c >> 2, seg = c & 3;
                uint32_t dst = st + m * MAT_B + row * ROWB + seg * 16;
                const char* sp = (const char*)(srcs[m] + (size_t)row * K + k0) + seg * 16;
                CP_ASYNC16(dst, __cvta_generic_to_global(sp));
            }
        }
    };

    auto compute = [&](int stage) {
        uint32_t st = sbase + stage * STAGE_BYTES;
        uint32_t lrow16 = (lane & 15);
        uint32_t lseg   = (lane >> 4) << 4;
#pragma unroll
        for (int s = 0; s < 2; s++) {            // two k16 steps in BK=32
            uint32_t kb = s * 32 + lseg;
            uint32_t a[2][4];
#pragma unroll
            for (int g = 0; g < 2; g++) {
                uint32_t row = wm * 32 + g * 16 + lrow16;
                ldsm4(st + row * ROWB + kb, a[g][0], a[g][1], a[g][2], a[g][3]);
            }
            uint32_t bh[4][4], bl[4][4];
#pragma unroll
            for (int g = 0; g < 4; g++) {
                uint32_t row = wn * 64 + g * 16 + lrow16;
                ldsm4(st + 1 * MAT_B + row * ROWB + kb, bh[g][0], bh[g][1], bh[g][2], bh[g][3]);
                ldsm4(st + 2 * MAT_B + row * ROWB + kb, bl[g][0], bl[g][1], bl[g][2], bl[g][3]);
            }
#pragma unroll
            for (int mg = 0; mg < 2; mg++)
#pragma unroll
                for (int g = 0; g < 4; g++) {
                    mma16816(acc[mg][2 * g + 0], a[mg], bh[g][0], bh[g][2]);
                    mma16816(acc[mg][2 * g + 1], a[mg], bh[g][1], bh[g][3]);
                    mma16816(acc[mg][2 * g + 0], a[mg], bl[g][0], bl[g][2]);
                    mma16816(acc[mg][2 * g + 1], a[mg], bl[g][1], bl[g][3]);
                }
        }
    };

    const int NC = K / BK;                        // 192
    fill(0, 0);      CP_COMMIT();
    fill(1, BK);     CP_COMMIT();

    for (int c = 0; c < NC; c++) {
        CP_WAIT(1);
        __syncthreads();
        if (c + 2 < NC) fill((c + 2) % STAGES, (c + 2) * BK);
        CP_COMMIT();
        compute(c % STAGES);
    }

    // epilogue: add bias, store fp32
#pragma unroll
    for (int mg = 0; mg < 2; mg++) {
        int row = brow + wm * 32 + mg * 16 + (lane >> 2);
#pragma unroll
        for (int g = 0; g < 8; g++) {
            int col = bcol + wn * 64 + g * 8 + (lane & 3) * 2;
            float2 bb = *reinterpret_cast<const float2*>(bias + col);
            float2 o0, o1;
            o0.x = acc[mg][g][0] + bb.x;
            o0.y = acc[mg][g][1] + bb.y;
            o1.x = acc[mg][g][2] + bb.x;
            o1.y = acc[mg][g][3] + bb.y;
            *reinterpret_cast<float2*>(C + (size_t)row * N + col)       = o0;
            *reinterpret_cast<float2*>(C + (size_t)(row + 8) * N + col) = o1;
        }
    }
}

// ---------------- host launcher ----------------------------------------------
extern "C" void kernel_launch(void* const* d_in, const int* in_sizes, int n_in,
                              void* d_out, int out_size)
{
    const float* x       = (const float*)d_in[0];
    const float* coeff1  = (const float*)d_in[1];
    const float* base_w1 = (const float*)d_in[2];
    const float* bias1   = (const float*)d_in[3];
    const float* gamma   = (const float*)d_in[4];
    const float* beta    = (const float*)d_in[5];
    const float* coeff2  = (const float*)d_in[6];
    const float* base_w2 = (const float*)d_in[7];
    const float* bias2   = (const float*)d_in[8];
    float* out = (float*)d_out;

    __half *F, *W1h, *W1l, *W2h, *W2l;
    float *H, *b1, *b2;
    cudaGetSymbolAddress((void**)&F,   g_F);
    cudaGetSymbolAddress((void**)&H,   g_H);
    cudaGetSymbolAddress((void**)&W1h, g_W1h);
    cudaGetSymbolAddress((void**)&W1l, g_W1l);
    cudaGetSymbolAddress((void**)&W2h, g_W2h);
    cudaGetSymbolAddress((void**)&W2l, g_W2l);
    cudaGetSymbolAddress((void**)&b1,  g_b1);
    cudaGetSymbolAddress((void**)&b2,  g_b2);

    // Idempotent; called every launch (no static guards per harness rules).
    cudaFuncSetAttribute(gemm_hsplit, cudaFuncAttributeMaxDynamicSharedMemorySize,
                         GEMM_SMEM);

    // 1. weight prep
    k_wprep<<<D1, 256>>>(coeff1, base_w1, W1h, W1l, D0);
    k_wprep<<<D2, 256>>>(coeff2, base_w2, W2h, W2l, D1);
    k_bias_eff<<<D1, 256>>>(coeff1, bias1, b1, D0);
    k_bias_eff<<<D2, 256>>>(coeff2, bias2, b2, D1);

    // 2. input features
    k_feat_in<<<(BATCH * D0 + 255) / 256, 256>>>(x, F);

    // 3. GEMM1: H = F * W1^T + b1   (M=16384, N=1024, K=6144)
    {
        dim3 grid(D1 / 128, BATCH / 128);
        gemm_hsplit<<<grid, 256, GEMM_SMEM>>>(F, W1h, W1l, b1, H, D1, KDIM);
    }

    // 4. LayerNorm + SiLU + features (rewrite F)
    k_ln_silu_feat<<<BATCH, 256>>>(H, gamma, beta, F);

    // 5. GEMM2: out = F * W2^T + b2  (M=16384, N=512, K=6144)
    {
        dim3 grid(D2 / 128, BATCH / 128);
        gemm_hsplit<<<grid, 256, GEMM_SMEM>>>(F, W2h, W2l, b2, out, D2, KDIM);
    }
}

// round 10
// speedup vs baseline: 6.2955x; 1.7303x over previous
#include <cuda_runtime.h>
#include <cuda_fp16.h>
#include <cstdint>
#include <math.h>

// Problem constants
#define BATCH 16384
#define D0    1024
#define D1    1024
#define D2    512
#define KDIM  6144     // 6 feature planes (T1..T5 + base); T0 folded into bias
#define LN_EPS 1e-5f

// GEMM tiling
#define BK    32
#define ROWB  80                         // bytes per smem row: 32 fp16 (64B) + 16B pad
#define MAT_B (128 * ROWB)               // one 128x32 fp16 tile = 10240 B
#define STAGE_BYTES (2 * MAT_B)          // F, W
#define STAGES 4
#define GEMM_SMEM (STAGES * STAGE_BYTES) // 81920 B

// ---------------- scratch (device globals; no runtime allocation) -------------
__device__ __half g_F  [(size_t)BATCH * KDIM];   // features fp16 (single plane)
__device__ float  g_H  [(size_t)BATCH * D1];     // layer-1 output (pre-LN)
__device__ __half g_W1 [(size_t)D1 * KDIM];
__device__ __half g_W2 [(size_t)D2 * KDIM];
__device__ float  g_b1[D1];
__device__ float  g_b2[D2];

// ---------------- helpers -----------------------------------------------------
__device__ __forceinline__ uint32_t smem_u32(const void* p) {
    uint32_t a;
    asm("{ .reg .u64 t; cvta.to.shared.u64 t, %1; cvt.u32.u64 %0, t; }" : "=r"(a) : "l"(p));
    return a;
}

#define CP_ASYNC16(dst, src) \
    asm volatile("cp.async.cg.shared.global [%0], [%1], 16;" \
                 :: "r"(dst), "l"(src) : "memory")
#define CP_COMMIT() asm volatile("cp.async.commit_group;" ::: "memory")
#define CP_WAIT(n)  asm volatile("cp.async.wait_group %0;" :: "n"(n) : "memory")

__device__ __forceinline__ void ldsm4(uint32_t addr, uint32_t& r0, uint32_t& r1,
                                      uint32_t& r2, uint32_t& r3) {
    asm volatile("ldmatrix.sync.aligned.m8n8.x4.shared.b16 {%0,%1,%2,%3}, [%4];"
                 : "=r"(r0), "=r"(r1), "=r"(r2), "=r"(r3) : "r"(addr));
}

__device__ __forceinline__ void mma16816(float* c, const uint32_t* a,
                                         uint32_t b0, uint32_t b1) {
    asm volatile("mma.sync.aligned.m16n8k16.row.col.f32.f16.f16.f32 "
                 "{%0,%1,%2,%3}, {%4,%5,%6,%7}, {%8,%9}, {%0,%1,%2,%3};"
                 : "+f"(c[0]), "+f"(c[1]), "+f"(c[2]), "+f"(c[3])
                 : "r"(a[0]), "r"(a[1]), "r"(a[2]), "r"(a[3]), "r"(b0), "r"(b1));
}

// ---------------- weight prep: W[o][k] fp16 -----------------------------------
// k = d*1024 + i ; plane d<5 -> coeff[o,i,d+1] ; plane 5 -> base_w[o,i]
__global__ __launch_bounds__(256) void k_wprep(const float* __restrict__ coeff,
                                               const float* __restrict__ basew,
                                               __half* __restrict__ W, int I)
{
    int o = blockIdx.x;
    int K = 6 * I;
    for (int i = threadIdx.x; i < I; i += 256) {
        const float* cp = coeff + ((size_t)o * I + i) * 6;
        float bw = basew[(size_t)o * I + i];
#pragma unroll
        for (int d = 0; d < 5; d++)
            W[(size_t)o * K + d * I + i] = __float2half_rn(cp[d + 1]);
        W[(size_t)o * K + 5 * I + i] = __float2half_rn(bw);
    }
}

// bias_eff[o] = bias[o] + sum_i coeff[o,i,0]
__global__ __launch_bounds__(256) void k_bias_eff(const float* __restrict__ coeff,
                                                  const float* __restrict__ bias,
                                                  float* __restrict__ out, int I)
{
    int o = blockIdx.x;
    int tid = threadIdx.x;
    float s = 0.f;
    for (int i = tid; i < I; i += 256)
        s += coeff[((size_t)o * I + i) * 6];
    __shared__ float sm[8];
    for (int off = 16; off > 0; off >>= 1) s += __shfl_down_sync(0xffffffffu, s, off);
    if ((tid & 31) == 0) sm[tid >> 5] = s;
    __syncthreads();
    if (tid < 8) {
        s = sm[tid];
        for (int off = 4; off > 0; off >>= 1) s += __shfl_down_sync(0xffu, s, off);
        if (tid == 0) out[o] = bias[o] + s;
    }
}

// ---------------- feature writers ---------------------------------------------
__device__ __forceinline__ void write_feats(float inp, size_t base,
                                            __half* __restrict__ F)
{
    float xn = tanhf(inp);
    float T1 = xn;
    float T2 = 2.f * xn * xn - 1.f;
    float T3 = 2.f * xn * T2 - T1;
    float T4 = 2.f * xn * T3 - T2;
    float T5 = 2.f * xn * T4 - T3;
    F[base + 0 * 1024] = __float2half_rn(T1);
    F[base + 1 * 1024] = __float2half_rn(T2);
    F[base + 2 * 1024] = __float2half_rn(T3);
    F[base + 3 * 1024] = __float2half_rn(T4);
    F[base + 4 * 1024] = __float2half_rn(T5);
    F[base + 5 * 1024] = __float2half_rn(inp);
}

__global__ __launch_bounds__(256) void k_feat_in(const float* __restrict__ x,
                                                 __half* __restrict__ F)
{
    int idx = blockIdx.x * 256 + threadIdx.x;
    if (idx >= BATCH * D0) return;
    int b = idx >> 10;
    int i = idx & 1023;
    float t = tanhf(x[idx]);
    write_feats(t, (size_t)b * KDIM + i, F);
}

__global__ __launch_bounds__(256) void k_ln_silu_feat(const float* __restrict__ H,
                                                      const float* __restrict__ gamma,
                                                      const float* __restrict__ beta,
                                                      __half* __restrict__ F)
{
    int b = blockIdx.x;
    int tid = threadIdx.x;
    const float* h = H + (size_t)b * D1;

    float v[4];
    float s = 0.f, sq = 0.f;
#pragma unroll
    for (int j = 0; j < 4; j++) {
        v[j] = h[tid + j * 256];
        s  += v[j];
        sq += v[j] * v[j];
    }
    __shared__ float sm_s[8], sm_q[8];
    for (int off = 16; off > 0; off >>= 1) {
        s  += __shfl_down_sync(0xffffffffu, s,  off);
        sq += __shfl_down_sync(0xffffffffu, sq, off);
    }
    if ((tid & 31) == 0) { sm_s[tid >> 5] = s; sm_q[tid >> 5] = sq; }
    __syncthreads();
    __shared__ float s_mu, s_rs;
    if (tid < 8) {
        s = sm_s[tid]; sq = sm_q[tid];
        for (int off = 4; off > 0; off >>= 1) {
            s  += __shfl_down_sync(0xffu, s,  off);
            sq += __shfl_down_sync(0xffu, sq, off);
        }
        if (tid == 0) {
            float mu = s * (1.f / D1);
            float var = sq * (1.f / D1) - mu * mu;
            s_mu = mu;
            s_rs = rsqrtf(var + LN_EPS);
        }
    }
    __syncthreads();
    float mu = s_mu, rs = s_rs;

#pragma unroll
    for (int j = 0; j < 4; j++) {
        int i = tid + j * 256;
        float y  = (v[j] - mu) * rs * gamma[i] + beta[i];
        float sg = 1.f / (1.f + expf(-y));
        float sv = y * sg;
        write_feats(sv, (size_t)b * KDIM + i, F);
    }
}

// ---------------- HMMA GEMM: C[M,N] = F * W^T + bias (fp16, 1 pass) -----------
// F[M,K] fp16; W[N,K] fp16; C fp32. 128x128x32 tiles, 4-stage cp.async.
__global__ __launch_bounds__(256, 2) void gemm_h(
    const __half* __restrict__ F, const __half* __restrict__ W,
    const float* __restrict__ bias, float* __restrict__ C, int N, int K)
{
    extern __shared__ char smem_raw[];
    uint32_t sbase = smem_u32(smem_raw);
    const int tid  = threadIdx.x;
    const int wid  = tid >> 5, lane = tid & 31;
    const int wm   = wid >> 1;       // 0..3 -> m offset 32*wm
    const int wn   = wid & 1;        // 0..1 -> n offset 64*wn
    const int brow = blockIdx.y * 128;
    const int bcol = blockIdx.x * 128;

    const __half* Ap = F + (size_t)brow * K;
    const __half* Bp = W + (size_t)bcol * K;

    float acc[2][8][4];
#pragma unroll
    for (int a = 0; a < 2; a++)
#pragma unroll
        for (int b = 0; b < 8; b++)
#pragma unroll
            for (int q = 0; q < 4; q++) acc[a][b][q] = 0.f;

    // fill one stage: 2 matrices x 128 rows x 64B (4x16B chunks/row)
    auto fill = [&](int stage, int k0) {
        uint32_t st = sbase + stage * STAGE_BYTES;
        const __half* srcs[2] = {Ap, Bp};
#pragma unroll
        for (int m = 0; m < 2; m++) {
#pragma unroll
            for (int j = 0; j < 2; j++) {
                int c   = tid + 256 * j;         // 0..511
                int row = c >> 2, seg = c & 3;
                uint32_t dst = st + m * MAT_B + row * ROWB + seg * 16;
                const char* sp = (const char*)(srcs[m] + (size_t)row * K + k0) + seg * 16;
                CP_ASYNC16(dst, __cvta_generic_to_global(sp));
            }
        }
    };

    auto compute = [&](int stage) {
        uint32_t st = sbase + stage * STAGE_BYTES;
        uint32_t lrow16 = (lane & 15);
        uint32_t lseg   = (lane >> 4) << 4;
#pragma unroll
        for (int s = 0; s < 2; s++) {            // two k16 steps in BK=32
            uint32_t kb = s * 32 + lseg;
            uint32_t a[2][4];
#pragma unroll
            for (int g = 0; g < 2; g++) {
                uint32_t row = wm * 32 + g * 16 + lrow16;
                ldsm4(st + row * ROWB + kb, a[g][0], a[g][1], a[g][2], a[g][3]);
            }
            uint32_t bh[4][4];
#pragma unroll
            for (int g = 0; g < 4; g++) {
                uint32_t row = wn * 64 + g * 16 + lrow16;
                ldsm4(st + 1 * MAT_B + row * ROWB + kb, bh[g][0], bh[g][1], bh[g][2], bh[g][3]);
            }
#pragma unroll
            for (int mg = 0; mg < 2; mg++)
#pragma unroll
                for (int g = 0; g < 4; g++) {
                    mma16816(acc[mg][2 * g + 0], a[mg], bh[g][0], bh[g][2]);
                    mma16816(acc[mg][2 * g + 1], a[mg], bh[g][1], bh[g][3]);
                }
        }
    };

    const int NC = K / BK;                        // 192
    fill(0, 0);       CP_COMMIT();
    fill(1, BK);      CP_COMMIT();
    fill(2, 2 * BK);  CP_COMMIT();

    for (int c = 0; c < NC; c++) {
        CP_WAIT(2);
        __syncthreads();
        if (c + 3 < NC) fill((c + 3) % STAGES, (c + 3) * BK);
        CP_COMMIT();
        compute(c % STAGES);
    }

    // epilogue: add bias, store fp32
#pragma unroll
    for (int mg = 0; mg < 2; mg++) {
        int row = brow + wm * 32 + mg * 16 + (lane >> 2);
#pragma unroll
        for (int g = 0; g < 8; g++) {
            int col = bcol + wn * 64 + g * 8 + (lane & 3) * 2;
            float2 bb = *reinterpret_cast<const float2*>(bias + col);
            float2 o0, o1;
            o0.x = acc[mg][g][0] + bb.x;
            o0.y = acc[mg][g][1] + bb.y;
            o1.x = acc[mg][g][2] + bb.x;
            o1.y = acc[mg][g][3] + bb.y;
            *reinterpret_cast<float2*>(C + (size_t)row * N + col)       = o0;
            *reinterpret_cast<float2*>(C + (size_t)(row + 8) * N + col) = o1;
        }
    }
}

// ---------------- host launcher ----------------------------------------------
extern "C" void kernel_launch(void* const* d_in, const int* in_sizes, int n_in,
                              void* d_out, int out_size)
{
    const float* x       = (const float*)d_in[0];
    const float* coeff1  = (const float*)d_in[1];
    const float* base_w1 = (const float*)d_in[2];
    const float* bias1   = (const float*)d_in[3];
    const float* gamma   = (const float*)d_in[4];
    const float* beta    = (const float*)d_in[5];
    const float* coeff2  = (const float*)d_in[6];
    const float* base_w2 = (const float*)d_in[7];
    const float* bias2   = (const float*)d_in[8];
    float* out = (float*)d_out;

    __half *F, *W1, *W2;
    float *H, *b1, *b2;
    cudaGetSymbolAddress((void**)&F,  g_F);
    cudaGetSymbolAddress((void**)&H,  g_H);
    cudaGetSymbolAddress((void**)&W1, g_W1);
    cudaGetSymbolAddress((void**)&W2, g_W2);
    cudaGetSymbolAddress((void**)&b1, g_b1);
    cudaGetSymbolAddress((void**)&b2, g_b2);

    // Idempotent; called every launch (no static guards per harness rules).
    cudaFuncSetAttribute(gemm_h, cudaFuncAttributeMaxDynamicSharedMemorySize,
                         GEMM_SMEM);

    // 1. weight prep
    k_wprep<<<D1, 256>>>(coeff1, base_w1, W1, D0);
    k_wprep<<<D2, 256>>>(coeff2, base_w2, W2, D1);
    k_bias_eff<<<D1, 256>>>(coeff1, bias1, b1, D0);
    k_bias_eff<<<D2, 256>>>(coeff2, bias2, b2, D1);

    // 2. input features
    k_feat_in<<<(BATCH * D0 + 255) / 256, 256>>>(x, F);

    // 3. GEMM1: H = F * W1^T + b1   (M=16384, N=1024, K=6144)
    {
        dim3 grid(D1 / 128, BATCH / 128);
        gemm_h<<<grid, 256, GEMM_SMEM>>>(F, W1, b1, H, D1, KDIM);
    }

    // 4. LayerNorm + SiLU + features (rewrite F)
    k_ln_silu_feat<<<BATCH, 256>>>(H, gamma, beta, F);

    // 5. GEMM2: out = F * W2^T + b2  (M=16384, N=512, K=6144)
    {
        dim3 grid(D2 / 128, BATCH / 128);
        gemm_h<<<grid, 256, GEMM_SMEM>>>(F, W2, b2, out, D2, KDIM);
    }
}